// round 3
// baseline (speedup 1.0000x reference)
#include <cuda_runtime.h>

#define DIM 128
#define MAX_GROUPS 50000
#define MAX_USERS  200000

// Scratch (device globals; no allocation allowed in kernel_launch)
__device__ float g_node_msg[MAX_GROUPS * DIM];
__device__ float g_msg[2][(size_t)MAX_GROUPS * DIM];
__device__ float g_user[2][(size_t)MAX_USERS * DIM];

// ---------------------------------------------------------------------------
// SpMM: out[dst[e]] += vals[e] * x[src[e]]   (one warp per edge, float4 lanes)
// ---------------------------------------------------------------------------
__global__ void spmm_kernel(const int* __restrict__ src, const int* __restrict__ dst,
                            const float* __restrict__ vals, const float4* __restrict__ x,
                            float* __restrict__ out, int nnz)
{
    long long t = (long long)blockIdx.x * blockDim.x + threadIdx.x;
    int e = (int)(t >> 5);
    if (e >= nnz) return;
    int lane = threadIdx.x & 31;

    int   s = __ldg(src + e);
    int   d = __ldg(dst + e);
    float v = __ldg(vals + e);

    float4 u = x[(long long)s * (DIM / 4) + lane];
    float* dp = out + (long long)d * DIM + lane * 4;
    asm volatile("red.global.add.v4.f32 [%0], {%1, %2, %3, %4};"
                 :: "l"(dp), "f"(u.x * v), "f"(u.y * v), "f"(u.z * v), "f"(u.w * v)
                 : "memory");
}

// ---------------------------------------------------------------------------
// Fused gated dense layer:
//   msg = concat(a, a*g) @ W + b ;  edge_sum += msg
// Persistent blocks, W (256x128 fp32 = 128KB) staged in dynamic smem.
// 256 threads: warp = row within 8-row tile, lane = 4-column group.
// ---------------------------------------------------------------------------
__global__ void gemm_gate_kernel(const float* __restrict__ node_msg,
                                 const float* __restrict__ group_cur,
                                 const float* __restrict__ W,     // [2*DIM][DIM]
                                 const float* __restrict__ bias,  // [DIM]
                                 float* __restrict__ msg_out,
                                 float* __restrict__ edge_sum,
                                 int n_groups)
{
    extern __shared__ float sm[];
    float* Wsm = sm;                 // 256*128 floats
    float* Xsm = sm + 2 * DIM * DIM; // 8 rows * 256 floats

    // Stage W once per block (vectorized)
    {
        const float4* Wv = (const float4*)W;
        float4* Wsv = (float4*)Wsm;
        for (int i = threadIdx.x; i < 2 * DIM * DIM / 4; i += blockDim.x)
            Wsv[i] = Wv[i];
    }
    __syncthreads();

    const int warp = threadIdx.x >> 5;   // row in tile (0..7)
    const int lane = threadIdx.x & 31;   // 4-col group (cols lane*4..lane*4+3)

    float4 bv = *(const float4*)(bias + lane * 4);

    for (int tile = blockIdx.x * 8; tile < n_groups; tile += gridDim.x * 8) {
        // Stage 8 rows of x = [a ; a*g]
        for (int i = threadIdx.x; i < 8 * DIM; i += blockDim.x) {
            int r = i >> 7;
            int k = i & (DIM - 1);
            int row = tile + r;
            float a = 0.f, g = 0.f;
            if (row < n_groups) {
                a = node_msg[(size_t)row * DIM + k];
                g = group_cur[(size_t)row * DIM + k];
            }
            Xsm[r * 2 * DIM + k]       = a;
            Xsm[r * 2 * DIM + DIM + k] = a * g;
        }
        __syncthreads();

        int row = tile + warp;
        float4 acc = bv;
        const float* xr = Xsm + warp * 2 * DIM;

        #pragma unroll 8
        for (int k = 0; k < 2 * DIM; k++) {
            float xs = xr[k];
            float4 w4 = *(const float4*)(Wsm + k * DIM + lane * 4);
            acc.x += xs * w4.x;
            acc.y += xs * w4.y;
            acc.z += xs * w4.z;
            acc.w += xs * w4.w;
        }

        if (row < n_groups) {
            float4* mo = (float4*)(msg_out + (size_t)row * DIM) + lane;
            *mo = acc;
            float4* es = (float4*)(edge_sum + (size_t)row * DIM) + lane;
            float4 e = *es;
            e.x += acc.x; e.y += acc.y; e.z += acc.z; e.w += acc.w;
            *es = e;
        }
        __syncthreads();
    }
}

// ---------------------------------------------------------------------------
// acc += x (vectorized)
// ---------------------------------------------------------------------------
__global__ void axpy_add_kernel(float4* __restrict__ acc, const float4* __restrict__ x, int n4)
{
    int i = blockIdx.x * blockDim.x + threadIdx.x;
    if (i < n4) {
        float4 a = acc[i];
        float4 b = x[i];
        a.x += b.x; a.y += b.y; a.z += b.z; a.w += b.w;
        acc[i] = a;
    }
}

// ---------------------------------------------------------------------------
extern "C" void kernel_launch(void* const* d_in, const int* in_sizes, int n_in,
                              void* d_out, int out_size)
{
    const float* group_emb = (const float*)d_in[0];
    const float* user_emb  = (const float*)d_in[1];
    const int*   rows      = (const int*)d_in[2];
    const int*   cols      = (const int*)d_in[3];
    const float* vals      = (const float*)d_in[4];
    const float* Ws        = (const float*)d_in[5];
    const float* bs        = (const float*)d_in[6];

    const int n_groups = in_sizes[0] / DIM;
    const int n_users  = in_sizes[1] / DIM;
    const int nnz      = in_sizes[2];
    const int layers   = in_sizes[6] / DIM;

    float* node_sum = (float*)d_out;                          // [n_users, DIM]
    float* edge_sum = (float*)d_out + (size_t)n_users * DIM;  // [n_groups, DIM]

    float *node_msg, *msg_base, *user_base;
    cudaGetSymbolAddress((void**)&node_msg, g_node_msg);
    cudaGetSymbolAddress((void**)&msg_base, g_msg);
    cudaGetSymbolAddress((void**)&user_base, g_user);
    float* msgb[2]  = { msg_base,  msg_base  + (size_t)MAX_GROUPS * DIM };
    float* userb[2] = { user_base, user_base + (size_t)MAX_USERS * DIM };

    // Initialize running sums with the input embeddings
    cudaMemcpyAsync(node_sum, user_emb, (size_t)n_users * DIM * sizeof(float),
                    cudaMemcpyDeviceToDevice, 0);
    cudaMemcpyAsync(edge_sum, group_emb, (size_t)n_groups * DIM * sizeof(float),
                    cudaMemcpyDeviceToDevice, 0);

    const int smem_bytes = (2 * DIM * DIM + 8 * 2 * DIM) * sizeof(float);
    cudaFuncSetAttribute(gemm_gate_kernel,
                         cudaFuncAttributeMaxDynamicSharedMemorySize, smem_bytes);

    const long long spmm_threads = (long long)nnz * 32;
    const int spmm_blocks = (int)((spmm_threads + 255) / 256);

    const float* user_cur  = user_emb;
    const float* group_cur = group_emb;
    int ub = 0, mb = 0;

    for (int i = 0; i < layers; i++) {
        // node_msg = H @ user_cur
        cudaMemsetAsync(node_msg, 0, (size_t)n_groups * DIM * sizeof(float), 0);
        spmm_kernel<<<spmm_blocks, 256>>>(cols, rows, vals,
                                          (const float4*)user_cur, node_msg, nnz);

        // msg = concat(node_msg, node_msg*group_cur) @ W[i] + b[i]; edge_sum += msg
        gemm_gate_kernel<<<148, 256, smem_bytes>>>(
            node_msg, group_cur,
            Ws + (size_t)i * 2 * DIM * DIM, bs + (size_t)i * DIM,
            msgb[mb], edge_sum, n_groups);

        // user_next = H^T @ msg ; node_sum += user_next
        float* user_next = userb[ub];
        cudaMemsetAsync(user_next, 0, (size_t)n_users * DIM * sizeof(float), 0);
        spmm_kernel<<<spmm_blocks, 256>>>(rows, cols, vals,
                                          (const float4*)msgb[mb], user_next, nnz);

        const int n4 = n_users * DIM / 4;
        axpy_add_kernel<<<(n4 + 255) / 256, 256>>>((float4*)node_sum,
                                                   (const float4*)user_next, n4);

        user_cur  = user_next;
        group_cur = msgb[mb];
        ub ^= 1;
        mb ^= 1;
    }
}

// round 4
// speedup vs baseline: 2.4048x; 2.4048x over previous
#include <cuda_runtime.h>
#include <cstddef>

#define DIM 128
#define MAX_GROUPS 50000
#define MAX_USERS  200000
#define MAX_NNZ    2000000

// ---------------------------------------------------------------------------
// Scratch (device globals; no allocation allowed)
// ---------------------------------------------------------------------------
__device__ float g_node_msg[(size_t)MAX_GROUPS * DIM];
__device__ float g_msg[2][(size_t)MAX_GROUPS * DIM];
__device__ float g_user[(size_t)MAX_USERS * DIM];

__device__ int  g_cntA[MAX_GROUPS];
__device__ int  g_ptrA[MAX_GROUPS + 1];
__device__ int  g_workA[MAX_GROUPS];
__device__ int  g_bsumA[256];
__device__ int2 g_ivA[MAX_NNZ];          // CSR by group row: (user_col, val)

__device__ int  g_cntB[MAX_USERS];
__device__ int  g_ptrB[MAX_USERS + 1];
__device__ int  g_workB[MAX_USERS];
__device__ int  g_bsumB[256];
__device__ int2 g_ivB[MAX_NNZ];          // CSC by user col: (group_row, val)

// ---------------------------------------------------------------------------
// CSR build: histogram -> 3-pass exclusive scan -> scatter
// ---------------------------------------------------------------------------
__global__ void hist_kernel(const int* __restrict__ rows, const int* __restrict__ cols,
                            int* __restrict__ cntA, int* __restrict__ cntB, int nnz)
{
    int i = blockIdx.x * blockDim.x + threadIdx.x;
    if (i < nnz) {
        atomicAdd(cntA + rows[i], 1);
        atomicAdd(cntB + cols[i], 1);
    }
}

// Inclusive scan per 1024-block; writes per-block inclusive results and block sums
__global__ void scan_block_kernel(const int* __restrict__ cnt, int* __restrict__ out,
                                  int* __restrict__ bsums, int n)
{
    __shared__ int sm[1024];
    int i = blockIdx.x * 1024 + threadIdx.x;
    int v = (i < n) ? cnt[i] : 0;
    sm[threadIdx.x] = v;
    __syncthreads();
    for (int off = 1; off < 1024; off <<= 1) {
        int t = (threadIdx.x >= off) ? sm[threadIdx.x - off] : 0;
        __syncthreads();
        sm[threadIdx.x] += t;
        __syncthreads();
    }
    if (i < n) out[i] = sm[threadIdx.x];
    if (threadIdx.x == 1023) bsums[blockIdx.x] = sm[1023];
}

// Exclusive scan of block sums in-place (nb <= 256), single block of 256 threads
__global__ void scan_small_kernel(int* __restrict__ bsums, int nb)
{
    __shared__ int sm[256];
    int v = (threadIdx.x < nb) ? bsums[threadIdx.x] : 0;
    sm[threadIdx.x] = v;
    __syncthreads();
    for (int off = 1; off < 256; off <<= 1) {
        int t = (threadIdx.x >= off) ? sm[threadIdx.x - off] : 0;
        __syncthreads();
        sm[threadIdx.x] += t;
        __syncthreads();
    }
    if (threadIdx.x < nb)
        bsums[threadIdx.x] = (threadIdx.x == 0) ? 0 : sm[threadIdx.x - 1];
}

__global__ void scan_add_kernel(int* __restrict__ out, const int* __restrict__ bsums, int n)
{
    int i = blockIdx.x * 1024 + threadIdx.x;
    if (i < n) out[i] += bsums[blockIdx.x];
}

__global__ void scatter_kernel(const int* __restrict__ rows, const int* __restrict__ cols,
                               const float* __restrict__ vals,
                               int* __restrict__ workA, int2* __restrict__ ivA,
                               int* __restrict__ workB, int2* __restrict__ ivB, int nnz)
{
    int i = blockIdx.x * blockDim.x + threadIdx.x;
    if (i >= nnz) return;
    int r = rows[i], c = cols[i];
    int v = __float_as_int(vals[i]);
    int pa = atomicAdd(workA + r, 1);
    ivA[pa] = make_int2(c, v);
    int pb = atomicAdd(workB + c, 1);
    ivB[pb] = make_int2(r, v);
}

// ---------------------------------------------------------------------------
// CSR SpMM: out[row] = sum_e val*x[idx]; optional sum_out[row] = sum_base[row]+acc
// Warp per row, lane owns a float4 (4 columns). Unroll-4 gathers for MLP.
// ---------------------------------------------------------------------------
__global__ void spmm_csr_kernel(const int* __restrict__ ptr, const int2* __restrict__ iv,
                                const float4* __restrict__ x, float4* __restrict__ out,
                                const float4* __restrict__ sum_base,
                                float4* __restrict__ sum_out, int n_rows)
{
    int row = blockIdx.x * (blockDim.x >> 5) + (threadIdx.x >> 5);
    if (row >= n_rows) return;
    const int lane = threadIdx.x & 31;

    int e   = __ldg(ptr + row);
    int end = __ldg(ptr + row + 1);

    float4 acc = make_float4(0.f, 0.f, 0.f, 0.f);

    for (; e + 4 <= end; e += 4) {
        int2 p0 = __ldg(iv + e);
        int2 p1 = __ldg(iv + e + 1);
        int2 p2 = __ldg(iv + e + 2);
        int2 p3 = __ldg(iv + e + 3);
        float4 u0 = __ldg(x + (size_t)p0.x * 32 + lane);
        float4 u1 = __ldg(x + (size_t)p1.x * 32 + lane);
        float4 u2 = __ldg(x + (size_t)p2.x * 32 + lane);
        float4 u3 = __ldg(x + (size_t)p3.x * 32 + lane);
        float v0 = __int_as_float(p0.y), v1 = __int_as_float(p1.y);
        float v2 = __int_as_float(p2.y), v3 = __int_as_float(p3.y);
        acc.x += v0 * u0.x; acc.y += v0 * u0.y; acc.z += v0 * u0.z; acc.w += v0 * u0.w;
        acc.x += v1 * u1.x; acc.y += v1 * u1.y; acc.z += v1 * u1.z; acc.w += v1 * u1.w;
        acc.x += v2 * u2.x; acc.y += v2 * u2.y; acc.z += v2 * u2.z; acc.w += v2 * u2.w;
        acc.x += v3 * u3.x; acc.y += v3 * u3.y; acc.z += v3 * u3.z; acc.w += v3 * u3.w;
    }
    for (; e < end; ++e) {
        int2 p = __ldg(iv + e);
        float v = __int_as_float(p.y);
        float4 u = __ldg(x + (size_t)p.x * 32 + lane);
        acc.x += v * u.x; acc.y += v * u.y; acc.z += v * u.z; acc.w += v * u.w;
    }

    size_t oidx = (size_t)row * 32 + lane;
    out[oidx] = acc;
    if (sum_out) {
        float4 b = __ldg(sum_base + oidx);
        b.x += acc.x; b.y += acc.y; b.z += acc.z; b.w += acc.w;
        sum_out[oidx] = b;
    }
}

// ---------------------------------------------------------------------------
// Fused gated dense layer:
//   msg = concat(a, a*g) @ W + b ;  edge_sum = ebase + msg
// Persistent 148 blocks; W (128KB) + X tile (32 rows, 32KB) in dynamic smem.
// 256 threads = 8 warps x 4 rows; lane owns 4 output columns.
// ---------------------------------------------------------------------------
__global__ void gemm_gate_kernel(const float* __restrict__ node_msg,
                                 const float* __restrict__ group_cur,
                                 const float* __restrict__ W,     // [2*DIM][DIM]
                                 const float* __restrict__ bias,  // [DIM]
                                 float* __restrict__ msg_out,
                                 const float* __restrict__ ebase,
                                 float* __restrict__ edge_sum,
                                 int n_groups)
{
    extern __shared__ float sm[];
    float4* Wsv = (float4*)sm;                     // 2*DIM*DIM floats
    float4* Xsv = (float4*)(sm + 2 * DIM * DIM);   // 32 rows * 2*DIM floats

    {
        const float4* Wv = (const float4*)W;
        for (int i = threadIdx.x; i < 2 * DIM * DIM / 4; i += blockDim.x)
            Wsv[i] = Wv[i];
    }

    const int warp = threadIdx.x >> 5;
    const int lane = threadIdx.x & 31;
    const float4 bv = ((const float4*)bias)[lane];

    const float4* nm4 = (const float4*)node_msg;
    const float4* gc4 = (const float4*)group_cur;
    __syncthreads();

    for (int tile = blockIdx.x * 32; tile < n_groups; tile += gridDim.x * 32) {
        // Stage X = [a ; a*g] for 32 rows
        for (int i = threadIdx.x; i < 32 * 32; i += 256) {
            int rr = i >> 5;        // row in tile
            int kq = i & 31;        // float4 idx within DIM
            int row = tile + rr;
            float4 a = make_float4(0.f, 0.f, 0.f, 0.f);
            float4 g = make_float4(0.f, 0.f, 0.f, 0.f);
            if (row < n_groups) {
                a = nm4[(size_t)row * 32 + kq];
                g = gc4[(size_t)row * 32 + kq];
            }
            Xsv[rr * 64 + kq] = a;
            Xsv[rr * 64 + 32 + kq] = make_float4(a.x * g.x, a.y * g.y, a.z * g.z, a.w * g.w);
        }
        __syncthreads();

        float4 acc0 = bv, acc1 = bv, acc2 = bv, acc3 = bv;
        const float4* Xr = Xsv + warp * 4 * 64;

        #pragma unroll 4
        for (int k = 0; k < 2 * DIM; k += 4) {
            float4 x0 = Xr[(k >> 2)];
            float4 x1 = Xr[64 + (k >> 2)];
            float4 x2 = Xr[128 + (k >> 2)];
            float4 x3 = Xr[192 + (k >> 2)];
            float4 w;
            w = Wsv[(k + 0) * 32 + lane];
            acc0.x += x0.x * w.x; acc0.y += x0.x * w.y; acc0.z += x0.x * w.z; acc0.w += x0.x * w.w;
            acc1.x += x1.x * w.x; acc1.y += x1.x * w.y; acc1.z += x1.x * w.z; acc1.w += x1.x * w.w;
            acc2.x += x2.x * w.x; acc2.y += x2.x * w.y; acc2.z += x2.x * w.z; acc2.w += x2.x * w.w;
            acc3.x += x3.x * w.x; acc3.y += x3.x * w.y; acc3.z += x3.x * w.z; acc3.w += x3.x * w.w;
            w = Wsv[(k + 1) * 32 + lane];
            acc0.x += x0.y * w.x; acc0.y += x0.y * w.y; acc0.z += x0.y * w.z; acc0.w += x0.y * w.w;
            acc1.x += x1.y * w.x; acc1.y += x1.y * w.y; acc1.z += x1.y * w.z; acc1.w += x1.y * w.w;
            acc2.x += x2.y * w.x; acc2.y += x2.y * w.y; acc2.z += x2.y * w.z; acc2.w += x2.y * w.w;
            acc3.x += x3.y * w.x; acc3.y += x3.y * w.y; acc3.z += x3.y * w.z; acc3.w += x3.y * w.w;
            w = Wsv[(k + 2) * 32 + lane];
            acc0.x += x0.z * w.x; acc0.y += x0.z * w.y; acc0.z += x0.z * w.z; acc0.w += x0.z * w.w;
            acc1.x += x1.z * w.x; acc1.y += x1.z * w.y; acc1.z += x1.z * w.z; acc1.w += x1.z * w.w;
            acc2.x += x2.z * w.x; acc2.y += x2.z * w.y; acc2.z += x2.z * w.z; acc2.w += x2.z * w.w;
            acc3.x += x3.z * w.x; acc3.y += x3.z * w.y; acc3.z += x3.z * w.z; acc3.w += x3.z * w.w;
            w = Wsv[(k + 3) * 32 + lane];
            acc0.x += x0.w * w.x; acc0.y += x0.w * w.y; acc0.z += x0.w * w.z; acc0.w += x0.w * w.w;
            acc1.x += x1.w * w.x; acc1.y += x1.w * w.y; acc1.z += x1.w * w.z; acc1.w += x1.w * w.w;
            acc2.x += x2.w * w.x; acc2.y += x2.w * w.y; acc2.z += x2.w * w.z; acc2.w += x2.w * w.w;
            acc3.x += x3.w * w.x; acc3.y += x3.w * w.y; acc3.z += x3.w * w.z; acc3.w += x3.w * w.w;
        }

        float4* mo = (float4*)msg_out;
        const float4* eb = (const float4*)ebase;
        float4* es = (float4*)edge_sum;
        int r0 = tile + warp * 4;
        float4 accs[4] = { acc0, acc1, acc2, acc3 };
        #pragma unroll
        for (int r = 0; r < 4; r++) {
            int row = r0 + r;
            if (row < n_groups) {
                size_t oi = (size_t)row * 32 + lane;
                mo[oi] = accs[r];
                float4 e = __ldg(eb + oi);
                e.x += accs[r].x; e.y += accs[r].y; e.z += accs[r].z; e.w += accs[r].w;
                es[oi] = e;
            }
        }
        __syncthreads();
    }
}

// ---------------------------------------------------------------------------
extern "C" void kernel_launch(void* const* d_in, const int* in_sizes, int n_in,
                              void* d_out, int out_size)
{
    const float* group_emb = (const float*)d_in[0];
    const float* user_emb  = (const float*)d_in[1];
    const int*   rows      = (const int*)d_in[2];
    const int*   cols      = (const int*)d_in[3];
    const float* vals      = (const float*)d_in[4];
    const float* Ws        = (const float*)d_in[5];
    const float* bs        = (const float*)d_in[6];

    const int n_groups = in_sizes[0] / DIM;
    const int n_users  = in_sizes[1] / DIM;
    const int nnz      = in_sizes[2];
    const int layers   = in_sizes[6] / DIM;

    float* node_sum = (float*)d_out;                          // [n_users, DIM]
    float* edge_sum = (float*)d_out + (size_t)n_users * DIM;  // [n_groups, DIM]

    float *node_msg, *msg_base, *user_buf;
    int *cntA, *ptrA, *workA, *bsumA, *cntB, *ptrB, *workB, *bsumB;
    int2 *ivA, *ivB;
    cudaGetSymbolAddress((void**)&node_msg, g_node_msg);
    cudaGetSymbolAddress((void**)&msg_base, g_msg);
    cudaGetSymbolAddress((void**)&user_buf, g_user);
    cudaGetSymbolAddress((void**)&cntA,  g_cntA);
    cudaGetSymbolAddress((void**)&ptrA,  g_ptrA);
    cudaGetSymbolAddress((void**)&workA, g_workA);
    cudaGetSymbolAddress((void**)&bsumA, g_bsumA);
    cudaGetSymbolAddress((void**)&ivA,   g_ivA);
    cudaGetSymbolAddress((void**)&cntB,  g_cntB);
    cudaGetSymbolAddress((void**)&ptrB,  g_ptrB);
    cudaGetSymbolAddress((void**)&workB, g_workB);
    cudaGetSymbolAddress((void**)&bsumB, g_bsumB);
    cudaGetSymbolAddress((void**)&ivB,   g_ivB);

    float* msgb[2] = { msg_base, msg_base + (size_t)MAX_GROUPS * DIM };

    // ---- Build CSR (by group row) and CSC (by user col), in-graph ----
    cudaMemsetAsync(cntA, 0, (size_t)n_groups * sizeof(int), 0);
    cudaMemsetAsync(cntB, 0, (size_t)n_users * sizeof(int), 0);
    hist_kernel<<<(nnz + 255) / 256, 256>>>(rows, cols, cntA, cntB, nnz);

    const int nbA = (n_groups + 1023) / 1024;
    const int nbB = (n_users + 1023) / 1024;
    scan_block_kernel<<<nbA, 1024>>>(cntA, ptrA + 1, bsumA, n_groups);
    scan_small_kernel<<<1, 256>>>(bsumA, nbA);
    scan_add_kernel<<<nbA, 1024>>>(ptrA + 1, bsumA, n_groups);
    scan_block_kernel<<<nbB, 1024>>>(cntB, ptrB + 1, bsumB, n_users);
    scan_small_kernel<<<1, 256>>>(bsumB, nbB);
    scan_add_kernel<<<nbB, 1024>>>(ptrB + 1, bsumB, n_users);

    cudaMemsetAsync(ptrA, 0, sizeof(int), 0);
    cudaMemsetAsync(ptrB, 0, sizeof(int), 0);
    cudaMemcpyAsync(workA, ptrA, (size_t)n_groups * sizeof(int),
                    cudaMemcpyDeviceToDevice, 0);
    cudaMemcpyAsync(workB, ptrB, (size_t)n_users * sizeof(int),
                    cudaMemcpyDeviceToDevice, 0);

    scatter_kernel<<<(nnz + 255) / 256, 256>>>(rows, cols, vals, workA, ivA, workB, ivB, nnz);

    // ---- Layers ----
    const int smem_bytes = (2 * DIM * DIM + 32 * 2 * DIM) * sizeof(float);
    cudaFuncSetAttribute(gemm_gate_kernel,
                         cudaFuncAttributeMaxDynamicSharedMemorySize, smem_bytes);

    const int spmmA_blocks = (n_groups + 7) / 8;   // 8 rows per 256-thread block
    const int spmmB_blocks = (n_users + 7) / 8;

    const float* user_cur  = user_emb;
    const float* group_cur = group_emb;
    int mb = 0;

    for (int i = 0; i < layers; i++) {
        // node_msg = H @ user_cur   (no memset needed: every row written)
        spmm_csr_kernel<<<spmmA_blocks, 256>>>(ptrA, ivA, (const float4*)user_cur,
                                               (float4*)node_msg, nullptr, nullptr, n_groups);

        // msg = concat(node_msg, node_msg*group_cur) @ W[i] + b[i];
        // edge_sum = (i==0 ? group_emb : edge_sum) + msg
        const float* ebase = (i == 0) ? group_emb : edge_sum;
        gemm_gate_kernel<<<148, 256, smem_bytes>>>(
            node_msg, group_cur,
            Ws + (size_t)i * 2 * DIM * DIM, bs + (size_t)i * DIM,
            msgb[mb], ebase, edge_sum, n_groups);

        // user_buf = H^T @ msg ; node_sum = (i==0 ? user_emb : node_sum) + user_buf
        const float* nbase = (i == 0) ? user_emb : node_sum;
        spmm_csr_kernel<<<spmmB_blocks, 256>>>(ptrB, ivB, (const float4*)msgb[mb],
                                               (float4*)user_buf,
                                               (const float4*)nbase, (float4*)node_sum,
                                               n_users);

        user_cur  = user_buf;
        group_cur = msgb[mb];
        mb ^= 1;
    }
}

// round 6
// speedup vs baseline: 2.4491x; 1.0184x over previous
#include <cuda_runtime.h>
#include <cstddef>

#define DIM 128
#define MAX_GROUPS 50000
#define MAX_USERS  200000
#define MAX_NNZ    2000000

// ---------------------------------------------------------------------------
// Scratch (device globals; no allocation allowed)
// ---------------------------------------------------------------------------
__device__ float g_node_msg[(size_t)MAX_GROUPS * DIM];
__device__ float g_msg[2][(size_t)MAX_GROUPS * DIM];
__device__ float g_user[(size_t)MAX_USERS * DIM];

__device__ int  g_cntA[MAX_GROUPS];
__device__ int  g_ptrA[MAX_GROUPS + 1];
__device__ int  g_workA[MAX_GROUPS];
__device__ int  g_bsumA[256];
__device__ int2 g_ivA[MAX_NNZ];          // CSR by group row: (user_col, val)

__device__ int  g_cntB[MAX_USERS];
__device__ int  g_ptrB[MAX_USERS + 1];
__device__ int  g_workB[MAX_USERS];
__device__ int  g_bsumB[256];
__device__ int2 g_ivB[MAX_NNZ];          // CSC by user col: (group_row, val)

// ---------------------------------------------------------------------------
// f32x2 packed-math helpers (Blackwell FFMA2 — only reachable via PTX)
// ---------------------------------------------------------------------------
__device__ __forceinline__ unsigned long long pack2(float lo, float hi)
{
    unsigned long long r;
    asm("mov.b64 %0, {%1, %2};" : "=l"(r) : "f"(lo), "f"(hi));
    return r;
}
__device__ __forceinline__ void ffma2(unsigned long long& d,
                                      unsigned long long a, unsigned long long b)
{
    asm("fma.rn.f32x2 %0, %1, %2, %0;" : "+l"(d) : "l"(a), "l"(b));
}
__device__ __forceinline__ float2 unpack2(unsigned long long v)
{
    float2 r;
    asm("mov.b64 {%0, %1}, %2;" : "=f"(r.x), "=f"(r.y) : "l"(v));
    return r;
}

// ---------------------------------------------------------------------------
// CSR build: histogram -> 3-pass exclusive scan -> scatter
// ---------------------------------------------------------------------------
__global__ void hist_kernel(const int* __restrict__ rows, const int* __restrict__ cols,
                            int* __restrict__ cntA, int* __restrict__ cntB, int nnz)
{
    int i = blockIdx.x * blockDim.x + threadIdx.x;
    if (i < nnz) {
        atomicAdd(cntA + rows[i], 1);
        atomicAdd(cntB + cols[i], 1);
    }
}

__global__ void scan_block_kernel(const int* __restrict__ cnt, int* __restrict__ out,
                                  int* __restrict__ bsums, int n)
{
    __shared__ int sm[1024];
    int i = blockIdx.x * 1024 + threadIdx.x;
    int v = (i < n) ? cnt[i] : 0;
    sm[threadIdx.x] = v;
    __syncthreads();
    for (int off = 1; off < 1024; off <<= 1) {
        int t = (threadIdx.x >= off) ? sm[threadIdx.x - off] : 0;
        __syncthreads();
        sm[threadIdx.x] += t;
        __syncthreads();
    }
    if (i < n) out[i] = sm[threadIdx.x];
    if (threadIdx.x == 1023) bsums[blockIdx.x] = sm[1023];
}

__global__ void scan_small_kernel(int* __restrict__ bsums, int nb)
{
    __shared__ int sm[256];
    int v = (threadIdx.x < nb) ? bsums[threadIdx.x] : 0;
    sm[threadIdx.x] = v;
    __syncthreads();
    for (int off = 1; off < 256; off <<= 1) {
        int t = (threadIdx.x >= off) ? sm[threadIdx.x - off] : 0;
        __syncthreads();
        sm[threadIdx.x] += t;
        __syncthreads();
    }
    if (threadIdx.x < nb)
        bsums[threadIdx.x] = (threadIdx.x == 0) ? 0 : sm[threadIdx.x - 1];
}

// Adds block offsets; writes inclusive result to out (ptr+1) and the EXCLUSIVE
// start position (incl - cnt) to work — removes the two memcpys.
__global__ void scan_add_kernel(int* __restrict__ out, const int* __restrict__ bsums,
                                const int* __restrict__ cnt, int* __restrict__ work, int n)
{
    int i = blockIdx.x * 1024 + threadIdx.x;
    if (i < n) {
        int incl = out[i] + bsums[blockIdx.x];
        out[i] = incl;
        work[i] = incl - cnt[i];
    }
}

__global__ void scatter_kernel(const int* __restrict__ rows, const int* __restrict__ cols,
                               const float* __restrict__ vals,
                               int* __restrict__ workA, int2* __restrict__ ivA,
                               int* __restrict__ workB, int2* __restrict__ ivB, int nnz)
{
    int i = blockIdx.x * blockDim.x + threadIdx.x;
    if (i >= nnz) return;
    int r = rows[i], c = cols[i];
    int v = __float_as_int(vals[i]);
    int pa = atomicAdd(workA + r, 1);
    ivA[pa] = make_int2(c, v);
    int pb = atomicAdd(workB + c, 1);
    ivB[pb] = make_int2(r, v);
}

// ---------------------------------------------------------------------------
// CSR SpMM: acc = sum_e val*x[idx];
//   if (out)     out[row]     = acc
//   if (sum_out) sum_out[row] = sum_base[row] + acc
// Warp per row, lane owns a float4 (4 columns). Unroll-4 gathers for MLP.
// ---------------------------------------------------------------------------
__global__ void spmm_csr_kernel(const int* __restrict__ ptr, const int2* __restrict__ iv,
                                const float4* __restrict__ x, float4* __restrict__ out,
                                const float4* __restrict__ sum_base,
                                float4* __restrict__ sum_out, int n_rows)
{
    int row = blockIdx.x * (blockDim.x >> 5) + (threadIdx.x >> 5);
    if (row >= n_rows) return;
    const int lane = threadIdx.x & 31;

    int e   = __ldg(ptr + row);
    int end = __ldg(ptr + row + 1);

    float4 acc = make_float4(0.f, 0.f, 0.f, 0.f);

    for (; e + 4 <= end; e += 4) {
        int2 p0 = __ldg(iv + e);
        int2 p1 = __ldg(iv + e + 1);
        int2 p2 = __ldg(iv + e + 2);
        int2 p3 = __ldg(iv + e + 3);
        float4 u0 = __ldg(x + (size_t)p0.x * 32 + lane);
        float4 u1 = __ldg(x + (size_t)p1.x * 32 + lane);
        float4 u2 = __ldg(x + (size_t)p2.x * 32 + lane);
        float4 u3 = __ldg(x + (size_t)p3.x * 32 + lane);
        float v0 = __int_as_float(p0.y), v1 = __int_as_float(p1.y);
        float v2 = __int_as_float(p2.y), v3 = __int_as_float(p3.y);
        acc.x += v0 * u0.x; acc.y += v0 * u0.y; acc.z += v0 * u0.z; acc.w += v0 * u0.w;
        acc.x += v1 * u1.x; acc.y += v1 * u1.y; acc.z += v1 * u1.z; acc.w += v1 * u1.w;
        acc.x += v2 * u2.x; acc.y += v2 * u2.y; acc.z += v2 * u2.z; acc.w += v2 * u2.w;
        acc.x += v3 * u3.x; acc.y += v3 * u3.y; acc.z += v3 * u3.z; acc.w += v3 * u3.w;
    }
    for (; e < end; ++e) {
        int2 p = __ldg(iv + e);
        float v = __int_as_float(p.y);
        float4 u = __ldg(x + (size_t)p.x * 32 + lane);
        acc.x += v * u.x; acc.y += v * u.y; acc.z += v * u.z; acc.w += v * u.w;
    }

    size_t oidx = (size_t)row * 32 + lane;
    if (out) out[oidx] = acc;
    if (sum_out) {
        float4 b = __ldg(sum_base + oidx);
        b.x += acc.x; b.y += acc.y; b.z += acc.z; b.w += acc.w;
        sum_out[oidx] = b;
    }
}

// ---------------------------------------------------------------------------
// Fused gated dense layer with packed FFMA2:
//   msg = concat(a, a*g) @ W + b ;  edge_sum = ebase + msg
// Persistent 148 blocks; W (128KB) + X tile (64 rows, 64KB) in dynamic smem.
// 256 threads = 8 warps x 8 rows; lane owns 4 output columns as 2x f32x2.
// ---------------------------------------------------------------------------
__global__ void gemm_gate_kernel(const float* __restrict__ node_msg,
                                 const float* __restrict__ group_cur,
                                 const float* __restrict__ W,     // [2*DIM][DIM]
                                 const float* __restrict__ bias,  // [DIM]
                                 float* __restrict__ msg_out,
                                 const float* __restrict__ ebase,
                                 float* __restrict__ edge_sum,
                                 int n_groups)
{
    extern __shared__ float sm[];
    float4* Wsv = (float4*)sm;                     // 2*DIM*DIM floats (128 KB)
    float4* Xsv = (float4*)(sm + 2 * DIM * DIM);   // 64 rows * 2*DIM floats (64 KB)

    {
        const float4* Wv = (const float4*)W;
        for (int i = threadIdx.x; i < 2 * DIM * DIM / 4; i += blockDim.x)
            Wsv[i] = Wv[i];
    }

    const int warp = threadIdx.x >> 5;
    const int lane = threadIdx.x & 31;
    const float4 bv = ((const float4*)bias)[lane];
    const unsigned long long b_lo = pack2(bv.x, bv.y);
    const unsigned long long b_hi = pack2(bv.z, bv.w);

    const float4* nm4 = (const float4*)node_msg;
    const float4* gc4 = (const float4*)group_cur;
    __syncthreads();

    for (int tile = blockIdx.x * 64; tile < n_groups; tile += gridDim.x * 64) {
        // Stage X = [a ; a*g] for 64 rows (2048 float4 per half)
        for (int i = threadIdx.x; i < 64 * 32; i += 256) {
            int rr = i >> 5;        // row in tile
            int kq = i & 31;        // float4 idx within DIM
            int row = tile + rr;
            float4 a = make_float4(0.f, 0.f, 0.f, 0.f);
            float4 g = make_float4(0.f, 0.f, 0.f, 0.f);
            if (row < n_groups) {
                a = nm4[(size_t)row * 32 + kq];
                g = gc4[(size_t)row * 32 + kq];
            }
            Xsv[rr * 64 + kq] = a;
            Xsv[rr * 64 + 32 + kq] = make_float4(a.x * g.x, a.y * g.y, a.z * g.z, a.w * g.w);
        }
        __syncthreads();

        unsigned long long acc_lo[8], acc_hi[8];
        #pragma unroll
        for (int r = 0; r < 8; r++) { acc_lo[r] = b_lo; acc_hi[r] = b_hi; }

        const float4* Xr = Xsv + warp * 8 * 64;   // this warp's 8 rows

        #pragma unroll 1
        for (int kq = 0; kq < 64; kq++) {         // each kq covers 4 k values
            float4 xr[8];
            #pragma unroll
            for (int r = 0; r < 8; r++) xr[r] = Xr[r * 64 + kq];

            #pragma unroll
            for (int j = 0; j < 4; j++) {
                float4 w = Wsv[(kq * 4 + j) * 32 + lane];
                unsigned long long w_lo = pack2(w.x, w.y);
                unsigned long long w_hi = pack2(w.z, w.w);
                #pragma unroll
                for (int r = 0; r < 8; r++) {
                    float xs = (j == 0) ? xr[r].x : (j == 1) ? xr[r].y
                             : (j == 2) ? xr[r].z : xr[r].w;
                    unsigned long long x2 = pack2(xs, xs);
                    ffma2(acc_lo[r], x2, w_lo);
                    ffma2(acc_hi[r], x2, w_hi);
                }
            }
        }

        float4* mo = (float4*)msg_out;
        const float4* eb = (const float4*)ebase;
        float4* es = (float4*)edge_sum;
        int r0 = tile + warp * 8;
        #pragma unroll
        for (int r = 0; r < 8; r++) {
            int row = r0 + r;
            if (row < n_groups) {
                float2 lo = unpack2(acc_lo[r]);
                float2 hi = unpack2(acc_hi[r]);
                float4 v = make_float4(lo.x, lo.y, hi.x, hi.y);
                size_t oi = (size_t)row * 32 + lane;
                mo[oi] = v;
                float4 e = __ldg(eb + oi);
                e.x += v.x; e.y += v.y; e.z += v.z; e.w += v.w;
                es[oi] = e;
            }
        }
        __syncthreads();
    }
}

// ---------------------------------------------------------------------------
extern "C" void kernel_launch(void* const* d_in, const int* in_sizes, int n_in,
                              void* d_out, int out_size)
{
    const float* group_emb = (const float*)d_in[0];
    const float* user_emb  = (const float*)d_in[1];
    const int*   rows      = (const int*)d_in[2];
    const int*   cols      = (const int*)d_in[3];
    const float* vals      = (const float*)d_in[4];
    const float* Ws        = (const float*)d_in[5];
    const float* bs        = (const float*)d_in[6];

    const int n_groups = in_sizes[0] / DIM;
    const int n_users  = in_sizes[1] / DIM;
    const int nnz      = in_sizes[2];
    const int layers   = in_sizes[6] / DIM;

    float* node_sum = (float*)d_out;                          // [n_users, DIM]
    float* edge_sum = (float*)d_out + (size_t)n_users * DIM;  // [n_groups, DIM]

    float *node_msg, *msg_base, *user_buf;
    int *cntA, *ptrA, *workA, *bsumA, *cntB, *ptrB, *workB, *bsumB;
    int2 *ivA, *ivB;
    cudaGetSymbolAddress((void**)&node_msg, g_node_msg);
    cudaGetSymbolAddress((void**)&msg_base, g_msg);
    cudaGetSymbolAddress((void**)&user_buf, g_user);
    cudaGetSymbolAddress((void**)&cntA,  g_cntA);
    cudaGetSymbolAddress((void**)&ptrA,  g_ptrA);
    cudaGetSymbolAddress((void**)&workA, g_workA);
    cudaGetSymbolAddress((void**)&bsumA, g_bsumA);
    cudaGetSymbolAddress((void**)&ivA,   g_ivA);
    cudaGetSymbolAddress((void**)&cntB,  g_cntB);
    cudaGetSymbolAddress((void**)&ptrB,  g_ptrB);
    cudaGetSymbolAddress((void**)&workB, g_workB);
    cudaGetSymbolAddress((void**)&bsumB, g_bsumB);
    cudaGetSymbolAddress((void**)&ivB,   g_ivB);

    float* msgb[2] = { msg_base, msg_base + (size_t)MAX_GROUPS * DIM };

    // ---- Build CSR (by group row) and CSC (by user col), in-graph ----
    cudaMemsetAsync(cntA, 0, (size_t)n_groups * sizeof(int), 0);
    cudaMemsetAsync(cntB, 0, (size_t)n_users * sizeof(int), 0);
    hist_kernel<<<(nnz + 255) / 256, 256>>>(rows, cols, cntA, cntB, nnz);

    const int nbA = (n_groups + 1023) / 1024;
    const int nbB = (n_users + 1023) / 1024;
    scan_block_kernel<<<nbA, 1024>>>(cntA, ptrA + 1, bsumA, n_groups);
    scan_small_kernel<<<1, 256>>>(bsumA, nbA);
    scan_add_kernel<<<nbA, 1024>>>(ptrA + 1, bsumA, cntA, workA, n_groups);
    scan_block_kernel<<<nbB, 1024>>>(cntB, ptrB + 1, bsumB, n_users);
    scan_small_kernel<<<1, 256>>>(bsumB, nbB);
    scan_add_kernel<<<nbB, 1024>>>(ptrB + 1, bsumB, cntB, workB, n_users);

    cudaMemsetAsync(ptrA, 0, sizeof(int), 0);
    cudaMemsetAsync(ptrB, 0, sizeof(int), 0);

    scatter_kernel<<<(nnz + 255) / 256, 256>>>(rows, cols, vals, workA, ivA, workB, ivB, nnz);

    // ---- Layers ----
    const int smem_bytes = (2 * DIM * DIM + 64 * 2 * DIM) * sizeof(float);
    cudaFuncSetAttribute(gemm_gate_kernel,
                         cudaFuncAttributeMaxDynamicSharedMemorySize, smem_bytes);

    const int spmmA_blocks = (n_groups + 7) / 8;   // 8 rows per 256-thread block
    const int spmmB_blocks = (n_users + 7) / 8;

    const float* user_cur  = user_emb;
    const float* group_cur = group_emb;
    int mb = 0;

    for (int i = 0; i < layers; i++) {
        // node_msg = H @ user_cur
        spmm_csr_kernel<<<spmmA_blocks, 256>>>(ptrA, ivA, (const float4*)user_cur,
                                               (float4*)node_msg, nullptr, nullptr, n_groups);

        // msg = concat(node_msg, node_msg*group_cur) @ W[i] + b[i];
        // edge_sum = (i==0 ? group_emb : edge_sum) + msg
        const float* ebase = (i == 0) ? group_emb : edge_sum;
        gemm_gate_kernel<<<148, 256, smem_bytes>>>(
            node_msg, group_cur,
            Ws + (size_t)i * 2 * DIM * DIM, bs + (size_t)i * DIM,
            msgb[mb], ebase, edge_sum, n_groups);

        // user_buf = H^T @ msg ; node_sum = (i==0 ? user_emb : node_sum) + user_buf
        // Last layer: user_buf is dead — skip the store.
        const float* nbase = (i == 0) ? user_emb : node_sum;
        float4* ubuf_out = (i == layers - 1) ? nullptr : (float4*)user_buf;
        spmm_csr_kernel<<<spmmB_blocks, 256>>>(ptrB, ivB, (const float4*)msgb[mb],
                                               ubuf_out,
                                               (const float4*)nbase, (float4*)node_sum,
                                               n_users);

        user_cur  = user_buf;
        group_cur = msgb[mb];
        mb ^= 1;
    }
}

// round 8
// speedup vs baseline: 2.7322x; 1.1156x over previous
#include <cuda_runtime.h>
#include <cuda_fp16.h>
#include <cstddef>

#define DIM 128
#define MAX_GROUPS 50000
#define MAX_USERS  200000
#define MAX_NNZ    2000000

#define H_SCALE   0.0009765625f   // 2^-10 (exact)
#define H_UNSCALE 1024.0f         // 2^10  (exact)

// ---------------------------------------------------------------------------
// Scratch (device globals; no allocation allowed)
// ---------------------------------------------------------------------------
__device__ float g_node_msg[(size_t)MAX_GROUPS * DIM];
__device__ __half g_userh[(size_t)MAX_USERS * DIM];          // fp16 user operand (scaled 2^-10)
__device__ __half g_msgh[3][(size_t)MAX_GROUPS * DIM];       // fp16 msg slots (scaled 2^-10)

__device__ int  g_cntA[MAX_GROUPS];
__device__ int  g_ptrA[MAX_GROUPS + 1];
__device__ int  g_workA[MAX_GROUPS];
__device__ int  g_bsumA[256];
__device__ int2 g_ivA[MAX_NNZ];          // CSR by group row: (user_col, val)

__device__ int  g_cntB[MAX_USERS];
__device__ int  g_ptrB[MAX_USERS + 1];
__device__ int  g_workB[MAX_USERS];
__device__ int  g_bsumB[256];
__device__ int2 g_ivB[MAX_NNZ];          // CSC by user col: (group_row, val)

// ---------------------------------------------------------------------------
// f32x2 packed-math helpers (Blackwell FFMA2 via PTX)
// ---------------------------------------------------------------------------
__device__ __forceinline__ unsigned long long pack2(float lo, float hi)
{
    unsigned long long r;
    asm("mov.b64 %0, {%1, %2};" : "=l"(r) : "f"(lo), "f"(hi));
    return r;
}
__device__ __forceinline__ void ffma2(unsigned long long& d,
                                      unsigned long long a, unsigned long long b)
{
    asm("fma.rn.f32x2 %0, %1, %2, %0;" : "+l"(d) : "l"(a), "l"(b));
}
__device__ __forceinline__ float2 unpack2(unsigned long long v)
{
    float2 r;
    asm("mov.b64 {%0, %1}, %2;" : "=f"(r.x), "=f"(r.y) : "l"(v));
    return r;
}

// unpack 4 halfs (uint2) -> float4
__device__ __forceinline__ float4 unpack_h4(uint2 raw)
{
    __half2 h0 = *reinterpret_cast<__half2*>(&raw.x);
    __half2 h1 = *reinterpret_cast<__half2*>(&raw.y);
    float2 a = __half22float2(h0);
    float2 b = __half22float2(h1);
    return make_float4(a.x, a.y, b.x, b.y);
}
// pack float4 -> 4 halfs (uint2)
__device__ __forceinline__ uint2 pack_h4(float4 v)
{
    __half2 h0 = __floats2half2_rn(v.x, v.y);
    __half2 h1 = __floats2half2_rn(v.z, v.w);
    uint2 r;
    r.x = *reinterpret_cast<unsigned*>(&h0);
    r.y = *reinterpret_cast<unsigned*>(&h1);
    return r;
}

// ---------------------------------------------------------------------------
// fp32 -> scaled fp16 (x * 2^-10, exact scaling)
__global__ void f32_to_f16_kernel(const float4* __restrict__ in, uint2* __restrict__ out, int n4)
{
    int i = blockIdx.x * blockDim.x + threadIdx.x;
    if (i < n4) {
        float4 v = in[i];
        v.x *= H_SCALE; v.y *= H_SCALE; v.z *= H_SCALE; v.w *= H_SCALE;
        out[i] = pack_h4(v);
    }
}

// ---------------------------------------------------------------------------
// CSR build: histogram -> 3-pass exclusive scan -> scatter
// ---------------------------------------------------------------------------
__global__ void hist_kernel(const int* __restrict__ rows, const int* __restrict__ cols,
                            int* __restrict__ cntA, int* __restrict__ cntB, int nnz)
{
    int i = blockIdx.x * blockDim.x + threadIdx.x;
    if (i < nnz) {
        atomicAdd(cntA + rows[i], 1);
        atomicAdd(cntB + cols[i], 1);
    }
}

__global__ void scan_block_kernel(const int* __restrict__ cnt, int* __restrict__ out,
                                  int* __restrict__ bsums, int n)
{
    __shared__ int sm[1024];
    int i = blockIdx.x * 1024 + threadIdx.x;
    int v = (i < n) ? cnt[i] : 0;
    sm[threadIdx.x] = v;
    __syncthreads();
    for (int off = 1; off < 1024; off <<= 1) {
        int t = (threadIdx.x >= off) ? sm[threadIdx.x - off] : 0;
        __syncthreads();
        sm[threadIdx.x] += t;
        __syncthreads();
    }
    if (i < n) out[i] = sm[threadIdx.x];
    if (threadIdx.x == 1023) bsums[blockIdx.x] = sm[1023];
}

__global__ void scan_small_kernel(int* __restrict__ bsums, int nb)
{
    __shared__ int sm[256];
    int v = (threadIdx.x < nb) ? bsums[threadIdx.x] : 0;
    sm[threadIdx.x] = v;
    __syncthreads();
    for (int off = 1; off < 256; off <<= 1) {
        int t = (threadIdx.x >= off) ? sm[threadIdx.x - off] : 0;
        __syncthreads();
        sm[threadIdx.x] += t;
        __syncthreads();
    }
    if (threadIdx.x < nb)
        bsums[threadIdx.x] = (threadIdx.x == 0) ? 0 : sm[threadIdx.x - 1];
}

__global__ void scan_add_kernel(int* __restrict__ out, const int* __restrict__ bsums,
                                const int* __restrict__ cnt, int* __restrict__ work, int n)
{
    int i = blockIdx.x * 1024 + threadIdx.x;
    if (i < n) {
        int incl = out[i] + bsums[blockIdx.x];
        out[i] = incl;
        work[i] = incl - cnt[i];
    }
}

__global__ void scatter_kernel(const int* __restrict__ rows, const int* __restrict__ cols,
                               const float* __restrict__ vals,
                               int* __restrict__ workA, int2* __restrict__ ivA,
                               int* __restrict__ workB, int2* __restrict__ ivB, int nnz)
{
    int i = blockIdx.x * blockDim.x + threadIdx.x;
    if (i >= nnz) return;
    int r = rows[i], c = cols[i];
    int v = __float_as_int(vals[i]);
    int pa = atomicAdd(workA + r, 1);
    ivA[pa] = make_int2(c, v);
    int pb = atomicAdd(workB + c, 1);
    ivB[pb] = make_int2(r, v);
}

// ---------------------------------------------------------------------------
// CSR SpMM with scaled-fp16 gather operand, fp32 accumulation:
//   acc_raw = sum_e val * xh[idx]          (xh holds true/1024)
//   acc_true = acc_raw * 1024              (exact)
//   if (out_f)   out_f[row]   = acc_true   (fp32)
//   if (out_h)   out_h[row]   = acc_raw    (fp16, already scaled — free)
//   if (sum_out) sum_out[row] = sum_base[row] + acc_true
// Warp per row; lane owns 4 columns (uint2 = 4 halfs).
// ---------------------------------------------------------------------------
__global__ void spmm_csr_h_kernel(const int* __restrict__ ptr, const int2* __restrict__ iv,
                                  const uint2* __restrict__ xh,
                                  float4* __restrict__ out_f, uint2* __restrict__ out_h,
                                  const float4* __restrict__ sum_base,
                                  float4* __restrict__ sum_out, int n_rows)
{
    int row = blockIdx.x * (blockDim.x >> 5) + (threadIdx.x >> 5);
    if (row >= n_rows) return;
    const int lane = threadIdx.x & 31;

    int e   = __ldg(ptr + row);
    int end = __ldg(ptr + row + 1);

    float4 acc = make_float4(0.f, 0.f, 0.f, 0.f);

    for (; e + 4 <= end; e += 4) {
        int2 p0 = __ldg(iv + e);
        int2 p1 = __ldg(iv + e + 1);
        int2 p2 = __ldg(iv + e + 2);
        int2 p3 = __ldg(iv + e + 3);
        uint2 r0 = __ldg(xh + (size_t)p0.x * 32 + lane);
        uint2 r1 = __ldg(xh + (size_t)p1.x * 32 + lane);
        uint2 r2 = __ldg(xh + (size_t)p2.x * 32 + lane);
        uint2 r3 = __ldg(xh + (size_t)p3.x * 32 + lane);
        float v0 = __int_as_float(p0.y), v1 = __int_as_float(p1.y);
        float v2 = __int_as_float(p2.y), v3 = __int_as_float(p3.y);
        float4 u0 = unpack_h4(r0);
        float4 u1 = unpack_h4(r1);
        float4 u2 = unpack_h4(r2);
        float4 u3 = unpack_h4(r3);
        acc.x += v0 * u0.x; acc.y += v0 * u0.y; acc.z += v0 * u0.z; acc.w += v0 * u0.w;
        acc.x += v1 * u1.x; acc.y += v1 * u1.y; acc.z += v1 * u1.z; acc.w += v1 * u1.w;
        acc.x += v2 * u2.x; acc.y += v2 * u2.y; acc.z += v2 * u2.z; acc.w += v2 * u2.w;
        acc.x += v3 * u3.x; acc.y += v3 * u3.y; acc.z += v3 * u3.z; acc.w += v3 * u3.w;
    }
    for (; e < end; ++e) {
        int2 p = __ldg(iv + e);
        float v = __int_as_float(p.y);
        float4 u = unpack_h4(__ldg(xh + (size_t)p.x * 32 + lane));
        acc.x += v * u.x; acc.y += v * u.y; acc.z += v * u.z; acc.w += v * u.w;
    }

    size_t oidx = (size_t)row * 32 + lane;
    if (out_h) out_h[oidx] = pack_h4(acc);   // still in scaled domain
    float4 at = make_float4(acc.x * H_UNSCALE, acc.y * H_UNSCALE,
                            acc.z * H_UNSCALE, acc.w * H_UNSCALE);
    if (out_f) out_f[oidx] = at;
    if (sum_out) {
        float4 b = __ldg(sum_base + oidx);
        b.x += at.x; b.y += at.y; b.z += at.z; b.w += at.w;
        sum_out[oidx] = b;
    }
}

// ---------------------------------------------------------------------------
// Fused gated dense layer with packed FFMA2:
//   msg = concat(a, a*g) @ W + b ;  msg_h = msg * 2^-10 (fp16);  edge_sum = ebase + msg
// a = node_msg (fp32), g = group_cur (scaled fp16 -> unscale folded into gating).
// Persistent 148 blocks; W (128KB) + X tile (64 rows, 64KB) in dynamic smem.
// 256 threads = 8 warps x 8 rows; lane owns 4 output columns as 2x f32x2.
// ---------------------------------------------------------------------------
__global__ void gemm_gate_kernel(const float* __restrict__ node_msg,
                                 const uint2* __restrict__ group_h,  // scaled fp16
                                 const float* __restrict__ W,        // [2*DIM][DIM]
                                 const float* __restrict__ bias,     // [DIM]
                                 uint2* __restrict__ msg_h,          // scaled fp16 out
                                 const float* __restrict__ ebase,
                                 float* __restrict__ edge_sum,
                                 int n_groups)
{
    extern __shared__ float sm[];
    float4* Wsv = (float4*)sm;                     // 2*DIM*DIM floats (128 KB)
    float4* Xsv = (float4*)(sm + 2 * DIM * DIM);   // 64 rows * 2*DIM floats (64 KB)

    {
        const float4* Wv = (const float4*)W;
        for (int i = threadIdx.x; i < 2 * DIM * DIM / 4; i += blockDim.x)
            Wsv[i] = Wv[i];
    }

    const int warp = threadIdx.x >> 5;
    const int lane = threadIdx.x & 31;
    const float4 bv = ((const float4*)bias)[lane];
    const unsigned long long b_lo = pack2(bv.x, bv.y);
    const unsigned long long b_hi = pack2(bv.z, bv.w);

    const float4* nm4 = (const float4*)node_msg;
    __syncthreads();

    for (int tile = blockIdx.x * 64; tile < n_groups; tile += gridDim.x * 64) {
        // Stage X = [a ; a*g_true] for 64 rows (g_true = g_scaled * 1024, exact)
        for (int i = threadIdx.x; i < 64 * 32; i += 256) {
            int rr = i >> 5;        // row in tile
            int kq = i & 31;        // float4 idx within DIM
            int row = tile + rr;
            float4 a = make_float4(0.f, 0.f, 0.f, 0.f);
            float4 g = make_float4(0.f, 0.f, 0.f, 0.f);
            if (row < n_groups) {
                a = nm4[(size_t)row * 32 + kq];
                g = unpack_h4(__ldg(group_h + (size_t)row * 32 + kq));
            }
            Xsv[rr * 64 + kq] = a;
            Xsv[rr * 64 + 32 + kq] =
                make_float4(a.x * g.x * H_UNSCALE, a.y * g.y * H_UNSCALE,
                            a.z * g.z * H_UNSCALE, a.w * g.w * H_UNSCALE);
        }
        __syncthreads();

        unsigned long long acc_lo[8], acc_hi[8];
        #pragma unroll
        for (int r = 0; r < 8; r++) { acc_lo[r] = b_lo; acc_hi[r] = b_hi; }

        const float4* Xr = Xsv + warp * 8 * 64;   // this warp's 8 rows

        #pragma unroll 1
        for (int kq = 0; kq < 64; kq++) {         // each kq covers 4 k values
            float4 xr[8];
            #pragma unroll
            for (int r = 0; r < 8; r++) xr[r] = Xr[r * 64 + kq];

            #pragma unroll
            for (int j = 0; j < 4; j++) {
                float4 w = Wsv[(kq * 4 + j) * 32 + lane];
                unsigned long long w_lo = pack2(w.x, w.y);
                unsigned long long w_hi = pack2(w.z, w.w);
                #pragma unroll
                for (int r = 0; r < 8; r++) {
                    float xs = (j == 0) ? xr[r].x : (j == 1) ? xr[r].y
                             : (j == 2) ? xr[r].z : xr[r].w;
                    unsigned long long x2 = pack2(xs, xs);
                    ffma2(acc_lo[r], x2, w_lo);
                    ffma2(acc_hi[r], x2, w_hi);
                }
            }
        }

        const float4* eb = (const float4*)ebase;
        float4* es = (float4*)edge_sum;
        int r0 = tile + warp * 8;
        #pragma unroll
        for (int r = 0; r < 8; r++) {
            int row = r0 + r;
            if (row < n_groups) {
                float2 lo = unpack2(acc_lo[r]);
                float2 hi = unpack2(acc_hi[r]);
                float4 v = make_float4(lo.x, lo.y, hi.x, hi.y);
                size_t oi = (size_t)row * 32 + lane;
                msg_h[oi] = pack_h4(make_float4(v.x * H_SCALE, v.y * H_SCALE,
                                                v.z * H_SCALE, v.w * H_SCALE));
                float4 e = __ldg(eb + oi);
                e.x += v.x; e.y += v.y; e.z += v.z; e.w += v.w;
                es[oi] = e;
            }
        }
        __syncthreads();
    }
}

// ---------------------------------------------------------------------------
extern "C" void kernel_launch(void* const* d_in, const int* in_sizes, int n_in,
                              void* d_out, int out_size)
{
    const float* group_emb = (const float*)d_in[0];
    const float* user_emb  = (const float*)d_in[1];
    const int*   rows      = (const int*)d_in[2];
    const int*   cols      = (const int*)d_in[3];
    const float* vals      = (const float*)d_in[4];
    const float* Ws        = (const float*)d_in[5];
    const float* bs        = (const float*)d_in[6];

    const int n_groups = in_sizes[0] / DIM;
    const int n_users  = in_sizes[1] / DIM;
    const int nnz      = in_sizes[2];
    const int layers   = in_sizes[6] / DIM;

    float* node_sum = (float*)d_out;                          // [n_users, DIM]
    float* edge_sum = (float*)d_out + (size_t)n_users * DIM;  // [n_groups, DIM]

    float* node_msg;
    __half *userh, *msgh_base;
    int *cntA, *ptrA, *workA, *bsumA, *cntB, *ptrB, *workB, *bsumB;
    int2 *ivA, *ivB;
    cudaGetSymbolAddress((void**)&node_msg, g_node_msg);
    cudaGetSymbolAddress((void**)&userh, g_userh);
    cudaGetSymbolAddress((void**)&msgh_base, g_msgh);
    cudaGetSymbolAddress((void**)&cntA,  g_cntA);
    cudaGetSymbolAddress((void**)&ptrA,  g_ptrA);
    cudaGetSymbolAddress((void**)&workA, g_workA);
    cudaGetSymbolAddress((void**)&bsumA, g_bsumA);
    cudaGetSymbolAddress((void**)&ivA,   g_ivA);
    cudaGetSymbolAddress((void**)&cntB,  g_cntB);
    cudaGetSymbolAddress((void**)&ptrB,  g_ptrB);
    cudaGetSymbolAddress((void**)&workB, g_workB);
    cudaGetSymbolAddress((void**)&bsumB, g_bsumB);
    cudaGetSymbolAddress((void**)&ivB,   g_ivB);

    __half* msgh[3] = { msgh_base,
                        msgh_base + (size_t)MAX_GROUPS * DIM,
                        msgh_base + 2 * (size_t)MAX_GROUPS * DIM };

    // ---- scaled fp16 conversions of the initial embeddings ----
    {
        int n4u = n_users * DIM / 4;
        f32_to_f16_kernel<<<(n4u + 255) / 256, 256>>>((const float4*)user_emb,
                                                      (uint2*)userh, n4u);
        int n4g = n_groups * DIM / 4;
        f32_to_f16_kernel<<<(n4g + 255) / 256, 256>>>((const float4*)group_emb,
                                                      (uint2*)msgh[2], n4g);
    }

    // ---- Build CSR (by group row) and CSC (by user col), in-graph ----
    cudaMemsetAsync(cntA, 0, (size_t)n_groups * sizeof(int), 0);
    cudaMemsetAsync(cntB, 0, (size_t)n_users * sizeof(int), 0);
    hist_kernel<<<(nnz + 255) / 256, 256>>>(rows, cols, cntA, cntB, nnz);

    const int nbA = (n_groups + 1023) / 1024;
    const int nbB = (n_users + 1023) / 1024;
    scan_block_kernel<<<nbA, 1024>>>(cntA, ptrA + 1, bsumA, n_groups);
    scan_small_kernel<<<1, 256>>>(bsumA, nbA);
    scan_add_kernel<<<nbA, 1024>>>(ptrA + 1, bsumA, cntA, workA, n_groups);
    scan_block_kernel<<<nbB, 1024>>>(cntB, ptrB + 1, bsumB, n_users);
    scan_small_kernel<<<1, 256>>>(bsumB, nbB);
    scan_add_kernel<<<nbB, 1024>>>(ptrB + 1, bsumB, cntB, workB, n_users);

    cudaMemsetAsync(ptrA, 0, sizeof(int), 0);
    cudaMemsetAsync(ptrB, 0, sizeof(int), 0);

    scatter_kernel<<<(nnz + 255) / 256, 256>>>(rows, cols, vals, workA, ivA, workB, ivB, nnz);

    // ---- Layers ----
    const int smem_bytes = (2 * DIM * DIM + 64 * 2 * DIM) * sizeof(float);
    cudaFuncSetAttribute(gemm_gate_kernel,
                         cudaFuncAttributeMaxDynamicSharedMemorySize, smem_bytes);

    const int spmmA_blocks = (n_groups + 7) / 8;   // 8 rows per 256-thread block
    const int spmmB_blocks = (n_users + 7) / 8;

    int cur = 2;   // group_cur slot (starts at converted group_emb)
    int nxt = 0;

    for (int i = 0; i < layers; i++) {
        // node_msg = H @ user_h   (scaled fp16 gather, fp32 out)
        spmm_csr_h_kernel<<<spmmA_blocks, 256>>>(ptrA, ivA, (const uint2*)userh,
                                                 (float4*)node_msg, nullptr,
                                                 nullptr, nullptr, n_groups);

        // msg_h = fp16(msg * 2^-10); edge_sum = (i==0 ? group_emb : edge_sum) + msg
        const float* ebase = (i == 0) ? group_emb : edge_sum;
        gemm_gate_kernel<<<148, 256, smem_bytes>>>(
            node_msg, (const uint2*)msgh[cur],
            Ws + (size_t)i * 2 * DIM * DIM, bs + (size_t)i * DIM,
            (uint2*)msgh[nxt], ebase, edge_sum, n_groups);

        // user_h = scaled fp16(H^T @ msg) ; node_sum = (i==0 ? user_emb : node_sum) + true
        // Last layer: user_h is dead — skip the fp16 store.
        const float* nbase = (i == 0) ? user_emb : node_sum;
        uint2* uh_out = (i == layers - 1) ? nullptr : (uint2*)userh;
        spmm_csr_h_kernel<<<spmmB_blocks, 256>>>(ptrB, ivB, (const uint2*)msgh[nxt],
                                                 nullptr, uh_out,
                                                 (const float4*)nbase, (float4*)node_sum,
                                                 n_users);

        cur = nxt;
        nxt = (nxt == 0) ? 1 : 0;
    }
}

// round 9
// speedup vs baseline: 2.9041x; 1.0629x over previous
#include <cuda_runtime.h>
#include <cuda_fp16.h>
#include <cstddef>

#define DIM 128
#define MAX_GROUPS 50000
#define MAX_USERS  200000
#define MAX_NNZ    2000000

#define H_SCALE   0.0009765625f   // 2^-10 (exact)
#define H_UNSCALE 1024.0f         // 2^10  (exact)

// ---------------------------------------------------------------------------
// Scratch (device globals; no allocation allowed)
// ---------------------------------------------------------------------------
__device__ float g_node_msg[(size_t)MAX_GROUPS * DIM];
__device__ __half g_userh[(size_t)MAX_USERS * DIM];          // fp16 user operand (scaled 2^-10)
__device__ __half g_msgh[3][(size_t)MAX_GROUPS * DIM];       // fp16 msg slots (scaled 2^-10)

__device__ int  g_cntA[MAX_GROUPS];
__device__ int  g_ptrA[MAX_GROUPS + 1];
__device__ int  g_workA[MAX_GROUPS];
__device__ int  g_bsumA[256];
__device__ int2 g_ivA[MAX_NNZ];          // CSR by group row: (user_col, val)

__device__ int  g_cntB[MAX_USERS];
__device__ int  g_ptrB[MAX_USERS + 1];
__device__ int  g_workB[MAX_USERS];
__device__ int  g_bsumB[256];
__device__ int2 g_ivB[MAX_NNZ];          // CSC by user col: (group_row, val)

// ---------------------------------------------------------------------------
// f32x2 packed-math helpers (Blackwell FFMA2 via PTX)
// ---------------------------------------------------------------------------
__device__ __forceinline__ unsigned long long pack2(float lo, float hi)
{
    unsigned long long r;
    asm("mov.b64 %0, {%1, %2};" : "=l"(r) : "f"(lo), "f"(hi));
    return r;
}
__device__ __forceinline__ void ffma2(unsigned long long& d,
                                      unsigned long long a, unsigned long long b)
{
    asm("fma.rn.f32x2 %0, %1, %2, %0;" : "+l"(d) : "l"(a), "l"(b));
}
__device__ __forceinline__ float2 unpack2(unsigned long long v)
{
    float2 r;
    asm("mov.b64 {%0, %1}, %2;" : "=f"(r.x), "=f"(r.y) : "l"(v));
    return r;
}

// unpack 4 halfs (uint2) -> float4
__device__ __forceinline__ float4 unpack_h4(unsigned lo, unsigned hi)
{
    __half2 h0 = *reinterpret_cast<__half2*>(&lo);
    __half2 h1 = *reinterpret_cast<__half2*>(&hi);
    float2 a = __half22float2(h0);
    float2 b = __half22float2(h1);
    return make_float4(a.x, a.y, b.x, b.y);
}
// pack float4 -> 4 halfs (uint2)
__device__ __forceinline__ uint2 pack_h4(float4 v)
{
    __half2 h0 = __floats2half2_rn(v.x, v.y);
    __half2 h1 = __floats2half2_rn(v.z, v.w);
    uint2 r;
    r.x = *reinterpret_cast<unsigned*>(&h0);
    r.y = *reinterpret_cast<unsigned*>(&h1);
    return r;
}

// ---------------------------------------------------------------------------
// fp32 -> scaled fp16 (x * 2^-10, exact scaling)
__global__ void f32_to_f16_kernel(const float4* __restrict__ in, uint2* __restrict__ out, int n4)
{
    int i = blockIdx.x * blockDim.x + threadIdx.x;
    if (i < n4) {
        float4 v = in[i];
        v.x *= H_SCALE; v.y *= H_SCALE; v.z *= H_SCALE; v.w *= H_SCALE;
        out[i] = pack_h4(v);
    }
}

// ---------------------------------------------------------------------------
// CSR build: histogram -> 3-pass exclusive scan -> scatter
// ---------------------------------------------------------------------------
__global__ void hist_kernel(const int* __restrict__ rows, const int* __restrict__ cols,
                            int* __restrict__ cntA, int* __restrict__ cntB, int nnz)
{
    int i = blockIdx.x * blockDim.x + threadIdx.x;
    if (i < nnz) {
        atomicAdd(cntA + rows[i], 1);
        atomicAdd(cntB + cols[i], 1);
    }
}

__global__ void scan_block_kernel(const int* __restrict__ cnt, int* __restrict__ out,
                                  int* __restrict__ bsums, int n)
{
    __shared__ int sm[1024];
    int i = blockIdx.x * 1024 + threadIdx.x;
    int v = (i < n) ? cnt[i] : 0;
    sm[threadIdx.x] = v;
    __syncthreads();
    for (int off = 1; off < 1024; off <<= 1) {
        int t = (threadIdx.x >= off) ? sm[threadIdx.x - off] : 0;
        __syncthreads();
        sm[threadIdx.x] += t;
        __syncthreads();
    }
    if (i < n) out[i] = sm[threadIdx.x];
    if (threadIdx.x == 1023) bsums[blockIdx.x] = sm[1023];
}

__global__ void scan_small_kernel(int* __restrict__ bsums, int nb)
{
    __shared__ int sm[256];
    int v = (threadIdx.x < nb) ? bsums[threadIdx.x] : 0;
    sm[threadIdx.x] = v;
    __syncthreads();
    for (int off = 1; off < 256; off <<= 1) {
        int t = (threadIdx.x >= off) ? sm[threadIdx.x - off] : 0;
        __syncthreads();
        sm[threadIdx.x] += t;
        __syncthreads();
    }
    if (threadIdx.x < nb)
        bsums[threadIdx.x] = (threadIdx.x == 0) ? 0 : sm[threadIdx.x - 1];
}

__global__ void scan_add_kernel(int* __restrict__ out, const int* __restrict__ bsums,
                                const int* __restrict__ cnt, int* __restrict__ work, int n)
{
    int i = blockIdx.x * 1024 + threadIdx.x;
    if (i < n) {
        int incl = out[i] + bsums[blockIdx.x];
        out[i] = incl;
        work[i] = incl - cnt[i];
    }
}

__global__ void scatter_kernel(const int* __restrict__ rows, const int* __restrict__ cols,
                               const float* __restrict__ vals,
                               int* __restrict__ workA, int2* __restrict__ ivA,
                               int* __restrict__ workB, int2* __restrict__ ivB, int nnz)
{
    int i = blockIdx.x * blockDim.x + threadIdx.x;
    if (i >= nnz) return;
    int r = rows[i], c = cols[i];
    int v = __float_as_int(vals[i]);
    int pa = atomicAdd(workA + r, 1);
    ivA[pa] = make_int2(c, v);
    int pb = atomicAdd(workB + c, 1);
    ivB[pb] = make_int2(r, v);
}

// ---------------------------------------------------------------------------
// CSR SpMM, HALF-WARP per row (16 lanes x LDG.128 = 256B fp16 row):
//   acc_raw = sum_e val * xh[idx]          (xh holds true/1024)
//   if (out_h)   out_h[row]   = acc_raw    (fp16, scaled domain — free)
//   if (out_f)   out_f[row]   = acc_raw * 1024
//   if (sum_out) sum_out[row] = sum_base[row] + acc_raw * 1024
// 2 independent rows per warp -> 8 outstanding gathers at unroll 4.
// Accumulation order per column identical to the 32-lane version.
// ---------------------------------------------------------------------------
__global__ __launch_bounds__(256)
void spmm_csr_h_kernel(const int* __restrict__ ptr, const int2* __restrict__ iv,
                       const uint4* __restrict__ xh,
                       float4* __restrict__ out_f, uint4* __restrict__ out_h,
                       const float4* __restrict__ sum_base,
                       float4* __restrict__ sum_out, int n_rows)
{
    int row = blockIdx.x * 16 + (threadIdx.x >> 4);
    if (row >= n_rows) return;
    const int lane = threadIdx.x & 15;   // owns 8 halfs (one uint4)

    int e   = __ldg(ptr + row);
    int end = __ldg(ptr + row + 1);

    float4 a0 = make_float4(0.f, 0.f, 0.f, 0.f);
    float4 a1 = make_float4(0.f, 0.f, 0.f, 0.f);

    for (; e + 4 <= end; e += 4) {
        int2 p0 = __ldg(iv + e);
        int2 p1 = __ldg(iv + e + 1);
        int2 p2 = __ldg(iv + e + 2);
        int2 p3 = __ldg(iv + e + 3);
        uint4 r0 = __ldg(xh + (size_t)p0.x * 16 + lane);
        uint4 r1 = __ldg(xh + (size_t)p1.x * 16 + lane);
        uint4 r2 = __ldg(xh + (size_t)p2.x * 16 + lane);
        uint4 r3 = __ldg(xh + (size_t)p3.x * 16 + lane);
        float v0 = __int_as_float(p0.y), v1 = __int_as_float(p1.y);
        float v2 = __int_as_float(p2.y), v3 = __int_as_float(p3.y);
        float4 u;
        u = unpack_h4(r0.x, r0.y);
        a0.x += v0 * u.x; a0.y += v0 * u.y; a0.z += v0 * u.z; a0.w += v0 * u.w;
        u = unpack_h4(r0.z, r0.w);
        a1.x += v0 * u.x; a1.y += v0 * u.y; a1.z += v0 * u.z; a1.w += v0 * u.w;
        u = unpack_h4(r1.x, r1.y);
        a0.x += v1 * u.x; a0.y += v1 * u.y; a0.z += v1 * u.z; a0.w += v1 * u.w;
        u = unpack_h4(r1.z, r1.w);
        a1.x += v1 * u.x; a1.y += v1 * u.y; a1.z += v1 * u.z; a1.w += v1 * u.w;
        u = unpack_h4(r2.x, r2.y);
        a0.x += v2 * u.x; a0.y += v2 * u.y; a0.z += v2 * u.z; a0.w += v2 * u.w;
        u = unpack_h4(r2.z, r2.w);
        a1.x += v2 * u.x; a1.y += v2 * u.y; a1.z += v2 * u.z; a1.w += v2 * u.w;
        u = unpack_h4(r3.x, r3.y);
        a0.x += v3 * u.x; a0.y += v3 * u.y; a0.z += v3 * u.z; a0.w += v3 * u.w;
        u = unpack_h4(r3.z, r3.w);
        a1.x += v3 * u.x; a1.y += v3 * u.y; a1.z += v3 * u.z; a1.w += v3 * u.w;
    }
    for (; e < end; ++e) {
        int2 p = __ldg(iv + e);
        float v = __int_as_float(p.y);
        uint4 r = __ldg(xh + (size_t)p.x * 16 + lane);
        float4 u;
        u = unpack_h4(r.x, r.y);
        a0.x += v * u.x; a0.y += v * u.y; a0.z += v * u.z; a0.w += v * u.w;
        u = unpack_h4(r.z, r.w);
        a1.x += v * u.x; a1.y += v * u.y; a1.z += v * u.z; a1.w += v * u.w;
    }

    size_t o = (size_t)row * 16 + lane;      // uint4-granular index (8 halfs)
    if (out_h) {
        uint2 h0 = pack_h4(a0);
        uint2 h1 = pack_h4(a1);
        out_h[o] = make_uint4(h0.x, h0.y, h1.x, h1.y);
    }
    float4 t0 = make_float4(a0.x * H_UNSCALE, a0.y * H_UNSCALE,
                            a0.z * H_UNSCALE, a0.w * H_UNSCALE);
    float4 t1 = make_float4(a1.x * H_UNSCALE, a1.y * H_UNSCALE,
                            a1.z * H_UNSCALE, a1.w * H_UNSCALE);
    if (out_f) {
        out_f[2 * o]     = t0;
        out_f[2 * o + 1] = t1;
    }
    if (sum_out) {
        float4 b0 = __ldg(sum_base + 2 * o);
        float4 b1 = __ldg(sum_base + 2 * o + 1);
        b0.x += t0.x; b0.y += t0.y; b0.z += t0.z; b0.w += t0.w;
        b1.x += t1.x; b1.y += t1.y; b1.z += t1.z; b1.w += t1.w;
        sum_out[2 * o]     = b0;
        sum_out[2 * o + 1] = b1;
    }
}

// ---------------------------------------------------------------------------
// Fused gated dense layer with packed FFMA2:
//   msg = concat(a, a*g) @ W + b ;  msg_h = msg * 2^-10 (fp16);  edge_sum = ebase + msg
// a = node_msg (fp32), g = group_cur (scaled fp16 -> unscale folded into gating).
// Persistent 148 blocks; W (128KB) + X tile (64 rows, 64KB) in dynamic smem.
// 256 threads = 8 warps x 8 rows; lane owns 4 output columns as 2x f32x2.
// ---------------------------------------------------------------------------
__global__ void gemm_gate_kernel(const float* __restrict__ node_msg,
                                 const uint2* __restrict__ group_h,  // scaled fp16
                                 const float* __restrict__ W,        // [2*DIM][DIM]
                                 const float* __restrict__ bias,     // [DIM]
                                 uint2* __restrict__ msg_h,          // scaled fp16 out
                                 const float* __restrict__ ebase,
                                 float* __restrict__ edge_sum,
                                 int n_groups)
{
    extern __shared__ float sm[];
    float4* Wsv = (float4*)sm;                     // 2*DIM*DIM floats (128 KB)
    float4* Xsv = (float4*)(sm + 2 * DIM * DIM);   // 64 rows * 2*DIM floats (64 KB)

    {
        const float4* Wv = (const float4*)W;
        for (int i = threadIdx.x; i < 2 * DIM * DIM / 4; i += blockDim.x)
            Wsv[i] = Wv[i];
    }

    const int warp = threadIdx.x >> 5;
    const int lane = threadIdx.x & 31;
    const float4 bv = ((const float4*)bias)[lane];
    const unsigned long long b_lo = pack2(bv.x, bv.y);
    const unsigned long long b_hi = pack2(bv.z, bv.w);

    const float4* nm4 = (const float4*)node_msg;
    __syncthreads();

    for (int tile = blockIdx.x * 64; tile < n_groups; tile += gridDim.x * 64) {
        // Stage X = [a ; a*g_true] for 64 rows (g_true = g_scaled * 1024, exact)
        for (int i = threadIdx.x; i < 64 * 32; i += 256) {
            int rr = i >> 5;        // row in tile
            int kq = i & 31;        // float4 idx within DIM
            int row = tile + rr;
            float4 a = make_float4(0.f, 0.f, 0.f, 0.f);
            float4 g = make_float4(0.f, 0.f, 0.f, 0.f);
            if (row < n_groups) {
                a = nm4[(size_t)row * 32 + kq];
                uint2 gr = __ldg(group_h + (size_t)row * 32 + kq);
                g = unpack_h4(gr.x, gr.y);
            }
            Xsv[rr * 64 + kq] = a;
            Xsv[rr * 64 + 32 + kq] =
                make_float4(a.x * g.x * H_UNSCALE, a.y * g.y * H_UNSCALE,
                            a.z * g.z * H_UNSCALE, a.w * g.w * H_UNSCALE);
        }
        __syncthreads();

        unsigned long long acc_lo[8], acc_hi[8];
        #pragma unroll
        for (int r = 0; r < 8; r++) { acc_lo[r] = b_lo; acc_hi[r] = b_hi; }

        const float4* Xr = Xsv + warp * 8 * 64;   // this warp's 8 rows

        #pragma unroll 1
        for (int kq = 0; kq < 64; kq++) {         // each kq covers 4 k values
            float4 xr[8];
            #pragma unroll
            for (int r = 0; r < 8; r++) xr[r] = Xr[r * 64 + kq];

            #pragma unroll
            for (int j = 0; j < 4; j++) {
                float4 w = Wsv[(kq * 4 + j) * 32 + lane];
                unsigned long long w_lo = pack2(w.x, w.y);
                unsigned long long w_hi = pack2(w.z, w.w);
                #pragma unroll
                for (int r = 0; r < 8; r++) {
                    float xs = (j == 0) ? xr[r].x : (j == 1) ? xr[r].y
                             : (j == 2) ? xr[r].z : xr[r].w;
                    unsigned long long x2 = pack2(xs, xs);
                    ffma2(acc_lo[r], x2, w_lo);
                    ffma2(acc_hi[r], x2, w_hi);
                }
            }
        }

        const float4* eb = (const float4*)ebase;
        float4* es = (float4*)edge_sum;
        int r0 = tile + warp * 8;
        #pragma unroll
        for (int r = 0; r < 8; r++) {
            int row = r0 + r;
            if (row < n_groups) {
                float2 lo = unpack2(acc_lo[r]);
                float2 hi = unpack2(acc_hi[r]);
                float4 v = make_float4(lo.x, lo.y, hi.x, hi.y);
                size_t oi = (size_t)row * 32 + lane;
                msg_h[oi] = pack_h4(make_float4(v.x * H_SCALE, v.y * H_SCALE,
                                                v.z * H_SCALE, v.w * H_SCALE));
                float4 e = __ldg(eb + oi);
                e.x += v.x; e.y += v.y; e.z += v.z; e.w += v.w;
                es[oi] = e;
            }
        }
        __syncthreads();
    }
}

// ---------------------------------------------------------------------------
extern "C" void kernel_launch(void* const* d_in, const int* in_sizes, int n_in,
                              void* d_out, int out_size)
{
    const float* group_emb = (const float*)d_in[0];
    const float* user_emb  = (const float*)d_in[1];
    const int*   rows      = (const int*)d_in[2];
    const int*   cols      = (const int*)d_in[3];
    const float* vals      = (const float*)d_in[4];
    const float* Ws        = (const float*)d_in[5];
    const float* bs        = (const float*)d_in[6];

    const int n_groups = in_sizes[0] / DIM;
    const int n_users  = in_sizes[1] / DIM;
    const int nnz      = in_sizes[2];
    const int layers   = in_sizes[6] / DIM;

    float* node_sum = (float*)d_out;                          // [n_users, DIM]
    float* edge_sum = (float*)d_out + (size_t)n_users * DIM;  // [n_groups, DIM]

    float* node_msg;
    __half *userh, *msgh_base;
    int *cntA, *ptrA, *workA, *bsumA, *cntB, *ptrB, *workB, *bsumB;
    int2 *ivA, *ivB;
    cudaGetSymbolAddress((void**)&node_msg, g_node_msg);
    cudaGetSymbolAddress((void**)&userh, g_userh);
    cudaGetSymbolAddress((void**)&msgh_base, g_msgh);
    cudaGetSymbolAddress((void**)&cntA,  g_cntA);
    cudaGetSymbolAddress((void**)&ptrA,  g_ptrA);
    cudaGetSymbolAddress((void**)&workA, g_workA);
    cudaGetSymbolAddress((void**)&bsumA, g_bsumA);
    cudaGetSymbolAddress((void**)&ivA,   g_ivA);
    cudaGetSymbolAddress((void**)&cntB,  g_cntB);
    cudaGetSymbolAddress((void**)&ptrB,  g_ptrB);
    cudaGetSymbolAddress((void**)&workB, g_workB);
    cudaGetSymbolAddress((void**)&bsumB, g_bsumB);
    cudaGetSymbolAddress((void**)&ivB,   g_ivB);

    __half* msgh[3] = { msgh_base,
                        msgh_base + (size_t)MAX_GROUPS * DIM,
                        msgh_base + 2 * (size_t)MAX_GROUPS * DIM };

    // ---- scaled fp16 conversions of the initial embeddings ----
    {
        int n4u = n_users * DIM / 4;
        f32_to_f16_kernel<<<(n4u + 255) / 256, 256>>>((const float4*)user_emb,
                                                      (uint2*)userh, n4u);
        int n4g = n_groups * DIM / 4;
        f32_to_f16_kernel<<<(n4g + 255) / 256, 256>>>((const float4*)group_emb,
                                                      (uint2*)msgh[2], n4g);
    }

    // ---- Build CSR (by group row) and CSC (by user col), in-graph ----
    cudaMemsetAsync(cntA, 0, (size_t)n_groups * sizeof(int), 0);
    cudaMemsetAsync(cntB, 0, (size_t)n_users * sizeof(int), 0);
    hist_kernel<<<(nnz + 255) / 256, 256>>>(rows, cols, cntA, cntB, nnz);

    const int nbA = (n_groups + 1023) / 1024;
    const int nbB = (n_users + 1023) / 1024;
    scan_block_kernel<<<nbA, 1024>>>(cntA, ptrA + 1, bsumA, n_groups);
    scan_small_kernel<<<1, 256>>>(bsumA, nbA);
    scan_add_kernel<<<nbA, 1024>>>(ptrA + 1, bsumA, cntA, workA, n_groups);
    scan_block_kernel<<<nbB, 1024>>>(cntB, ptrB + 1, bsumB, n_users);
    scan_small_kernel<<<1, 256>>>(bsumB, nbB);
    scan_add_kernel<<<nbB, 1024>>>(ptrB + 1, bsumB, cntB, workB, n_users);

    cudaMemsetAsync(ptrA, 0, sizeof(int), 0);
    cudaMemsetAsync(ptrB, 0, sizeof(int), 0);

    scatter_kernel<<<(nnz + 255) / 256, 256>>>(rows, cols, vals, workA, ivA, workB, ivB, nnz);

    // ---- Layers ----
    const int smem_bytes = (2 * DIM * DIM + 64 * 2 * DIM) * sizeof(float);
    cudaFuncSetAttribute(gemm_gate_kernel,
                         cudaFuncAttributeMaxDynamicSharedMemorySize, smem_bytes);

    const int spmmA_blocks = (n_groups + 15) / 16;   // 16 rows per 256-thread block
    const int spmmB_blocks = (n_users + 15) / 16;

    int cur = 2;   // group_cur slot (starts at converted group_emb)
    int nxt = 0;

    for (int i = 0; i < layers; i++) {
        // node_msg = H @ user_h   (scaled fp16 gather, fp32 out)
        spmm_csr_h_kernel<<<spmmA_blocks, 256>>>(ptrA, ivA, (const uint4*)userh,
                                                 (float4*)node_msg, nullptr,
                                                 nullptr, nullptr, n_groups);

        // msg_h = fp16(msg * 2^-10); edge_sum = (i==0 ? group_emb : edge_sum) + msg
        const float* ebase = (i == 0) ? group_emb : edge_sum;
        gemm_gate_kernel<<<148, 256, smem_bytes>>>(
            node_msg, (const uint2*)msgh[cur],
            Ws + (size_t)i * 2 * DIM * DIM, bs + (size_t)i * DIM,
            (uint2*)msgh[nxt], ebase, edge_sum, n_groups);

        // user_h = scaled fp16(H^T @ msg) ; node_sum = (i==0 ? user_emb : node_sum) + true
        // Last layer: user_h is dead — skip the fp16 store.
        const float* nbase = (i == 0) ? user_emb : node_sum;
        uint4* uh_out = (i == layers - 1) ? nullptr : (uint4*)userh;
        spmm_csr_h_kernel<<<spmmB_blocks, 256>>>(ptrB, ivB, (const uint4*)msgh[nxt],
                                                 nullptr, uh_out,
                                                 (const float4*)nbase, (float4*)node_sum,
                                                 n_users);

        cur = nxt;
        nxt = (nxt == 0) ? 1 : 0;
    }
}